// round 15
// baseline (speedup 1.0000x reference)
#include <cuda_runtime.h>
#include <cuda_bf16.h>
#include <cuda_fp16.h>
#include <math.h>
#include <stdint.h>

#define N_NODES 100000
#define F_IN    256
#define H1      128
#define H2      16
#define C_OUT   40
#define E_EDGES 3200000
#define E_TOT   (E_EDGES + N_NODES)
#define NBLK_N  ((N_NODES + 255) / 256)   // 391

// ---------------- scratch (static device arrays; no runtime alloc) ---------
__device__ __align__(16) __half g_h1[N_NODES * H1];     // x @ W1 (fp16)
__device__ __align__(16) __half g_h2[N_NODES * H2];     // fused agg1+gemm2 out
__device__ __align__(16) __half g_a2[N_NODES * H2];     // leaky(agg(h2)+b2) fp16
__device__ __align__(16) float  g_g3[N_NODES * H2];     // agg(a2) fp32
__device__ __align__(16) __nv_bfloat16 g_xhi[N_NODES * F_IN];  // X hi split
__device__ __align__(16) __nv_bfloat16 g_xlo[N_NODES * F_IN];  // X lo split
__device__ __align__(16) __nv_bfloat16 g_wt_hi[H1 * F_IN];  // W1^T hi [n][k]
__device__ __align__(16) __nv_bfloat16 g_wt_lo[H1 * F_IN];  // W1^T lo [n][k]
__device__ int   g_deg[N_NODES];          // zero at entry; hist adds; scan resets
__device__ float g_dis[N_NODES];          // deg^{-1/2}
__device__ int   g_rowptr[N_NODES + 1];
__device__ int   g_cursor[N_NODES];
__device__ __align__(8) int2 g_edge[E_TOT];   // (src, wgt-bits) per CSR slot
__device__ int   g_bsums[512];
__device__ int   g_boff[512];

#define LEAKY(v) ((v) > 0.f ? (v) : 0.2f * (v))

// ===================== portable tensor-core helpers (sm_80+) ================
__device__ __forceinline__ uint32_t smem_u32(const void* p) {
    uint32_t a;
    asm("{ .reg .u64 t; cvta.to.shared.u64 t, %1; cvt.u32.u64 %0, t; }"
        : "=r"(a) : "l"(p));
    return a;
}
__device__ __forceinline__ void ldmx4(uint32_t& r0, uint32_t& r1,
                                      uint32_t& r2, uint32_t& r3, uint32_t a) {
    asm volatile("ldmatrix.sync.aligned.m8n8.x4.shared.b16 {%0,%1,%2,%3}, [%4];"
                 : "=r"(r0), "=r"(r1), "=r"(r2), "=r"(r3) : "r"(a));
}
__device__ __forceinline__ void mma_bf16(float* d, const uint32_t* a,
                                         uint32_t b0, uint32_t b1) {
    asm volatile(
        "mma.sync.aligned.m16n8k16.row.col.f32.bf16.bf16.f32 "
        "{%0,%1,%2,%3}, {%4,%5,%6,%7}, {%8,%9}, {%0,%1,%2,%3};"
        : "+f"(d[0]), "+f"(d[1]), "+f"(d[2]), "+f"(d[3])
        : "r"(a[0]), "r"(a[1]), "r"(a[2]), "r"(a[3]), "r"(b0), "r"(b1));
}
#define CP16(dst, src) \
    asm volatile("cp.async.cg.shared.global [%0], [%1], 16;" \
                 :: "r"(dst), "l"(src) : "memory")
#define CP_COMMIT() asm volatile("cp.async.commit_group;" ::: "memory")

// ---------------- W1 transpose + bf16 split (side stream) ------------------
__global__ void k_prepw(const float* __restrict__ W1) {
    int i = blockIdx.x * blockDim.x + threadIdx.x;
    if (i < F_IN * H1) {
        int k = i >> 7, n = i & 127;
        float w = W1[i];
        __nv_bfloat16 hi = __float2bfloat16_rn(w);
        float lo = w - __bfloat162float(hi);
        g_wt_hi[n * F_IN + k] = hi;
        g_wt_lo[n * F_IN + k] = __float2bfloat16_rn(lo);
    }
}

// ---------------- X bf16 split (side stream, streams 204 MB) ----------------
__global__ __launch_bounds__(256) void k_prepx(const float* __restrict__ X) {
    int idx = blockIdx.x * blockDim.x + threadIdx.x;   // float4 group
    if (idx < N_NODES * F_IN / 4) {
        float4 v = ((const float4*)X)[idx];
        float f[4] = {v.x, v.y, v.z, v.w};
        unsigned short hb[4], lb[4];
#pragma unroll
        for (int q = 0; q < 4; q++) {
            __nv_bfloat16 h = __float2bfloat16_rn(f[q]);
            __nv_bfloat16 l = __float2bfloat16_rn(f[q] - __bfloat162float(h));
            hb[q] = *(unsigned short*)&h;
            lb[q] = *(unsigned short*)&l;
        }
        uint2 ph = make_uint2((uint32_t)hb[0] | ((uint32_t)hb[1] << 16),
                              (uint32_t)hb[2] | ((uint32_t)hb[3] << 16));
        uint2 pl = make_uint2((uint32_t)lb[0] | ((uint32_t)lb[1] << 16),
                              (uint32_t)lb[2] | ((uint32_t)lb[3] << 16));
        ((uint2*)g_xhi)[idx] = ph;
        ((uint2*)g_xlo)[idx] = pl;
    }
}

// ---------------- CSR: histogram (g_deg starts at 0) ------------------------
__global__ void k_hist(const int* __restrict__ ei) {
    int e = blockIdx.x * blockDim.x + threadIdx.x;
    if (e < E_EDGES) atomicAdd(&g_deg[ei[E_EDGES + e]], 1);
}

// ---------------- CSR: hierarchical scan ------------------------------------
__global__ void k_scan_block() {
    __shared__ int s[256];
    int b = blockIdx.x, t = threadIdx.x;
    int i = b * 256 + t;
    int v = 0;
    if (i < N_NODES) {
        v = g_deg[i] + 1;                 // +1 self loop
        g_deg[i] = 0;                     // reset for next graph replay
        g_dis[i] = rsqrtf((float)v);
    }
    s[t] = v;
    __syncthreads();
#pragma unroll
    for (int off = 1; off < 256; off <<= 1) {
        int add = (t >= off) ? s[t - off] : 0;
        __syncthreads();
        s[t] += add;
        __syncthreads();
    }
    int incl = s[t];
    if (i < N_NODES) g_rowptr[i] = incl - v;
    if (t == 255) g_bsums[b] = incl;
}
__global__ void k_scan_sums(int nblk) {
    __shared__ int s[512];
    int t = threadIdx.x;
    int v = (t < nblk) ? g_bsums[t] : 0;
    s[t] = v;
    __syncthreads();
#pragma unroll
    for (int off = 1; off < 512; off <<= 1) {
        int add = (t >= off) ? s[t - off] : 0;
        __syncthreads();
        s[t] += add;
        __syncthreads();
    }
    int incl = s[t];
    if (t < nblk) g_boff[t] = incl - v;
    if (t == 511) g_rowptr[N_NODES] = incl;
}
__global__ void k_scan_fixup() {
    int i = blockIdx.x * blockDim.x + threadIdx.x;
    if (i < N_NODES) {
        int v = g_rowptr[i] + g_boff[i >> 8];
        g_rowptr[i] = v;
        g_cursor[i] = v + 1;
        float d = g_dis[i];
        g_edge[v] = make_int2(i, __float_as_int(d * d));
    }
}
__global__ void k_fill_edge(const int* __restrict__ ei) {
    int e = blockIdx.x * blockDim.x + threadIdx.x;
    if (e < E_EDGES) {
        int s = ei[e];
        int d = ei[E_EDGES + e];
        int p = atomicAdd(&g_cursor[d], 1);
        float w = g_dis[s] * g_dis[d];
        g_edge[p] = make_int2(s, __float_as_int(w));
    }
}

// ---------------- GEMM1: h1 = X @ W1, cp.async double-buffer pipeline -------
#define PADK 40
#define ARR_B   10240                     // 128 rows * 80 B
#define BUF_B   (4 * ARR_B)               // Ahi,Alo,Bhi,Blo
#define SMEM_G1 (2 * BUF_B)               // 81920 bytes
__global__ __launch_bounds__(256, 2) void k_gemm1() {
    extern __shared__ char dsm[];
    const uint32_t dbase = smem_u32(dsm);

    const int tid = threadIdx.x, wid = tid >> 5, lane = tid & 31;
    const int wm = wid & 1, wn = wid >> 1;
    const int blockRow = blockIdx.x * 128;

    const int srow = tid >> 1;          // 0..127 (A row m, B row n)
    const int skh  = tid & 1;           // which 32B half of the 64B row chunk
    const int grow = blockRow + srow;
    const bool rowOK = (grow < N_NODES);
    const uint32_t soff = (uint32_t)(srow * 80 + skh * 32);

    const uint32_t aLaneOff =
        (uint32_t)((wm * 64 + (lane & 15)) * PADK + (lane >> 4) * 8) * 2;
    const uint32_t bLaneOff =
        (uint32_t)((wn * 32 + (lane & 7) + (lane >> 4) * 8) * PADK +
                   ((lane >> 3) & 1) * 8) * 2;

    float acc[4][4][4];
#pragma unroll
    for (int i = 0; i < 4; i++)
#pragma unroll
        for (int j = 0; j < 4; j++)
#pragma unroll
            for (int q = 0; q < 4; q++) acc[i][j][q] = 0.f;

    const char* srcXh = (const char*)g_xhi + (size_t)grow * 512 + skh * 32;
    const char* srcXl = (const char*)g_xlo + (size_t)grow * 512 + skh * 32;
    const char* srcWh = (const char*)g_wt_hi + (size_t)srow * 512 + skh * 32;
    const char* srcWl = (const char*)g_wt_lo + (size_t)srow * 512 + skh * 32;

    auto issue = [&](int c, int buf) {
        uint32_t d0 = dbase + (uint32_t)(buf * BUF_B) + soff;
        int g = c * 64;
        if (rowOK) {
            CP16(d0,                 srcXh + g);
            CP16(d0 + 16,            srcXh + g + 16);
            CP16(d0 + ARR_B,         srcXl + g);
            CP16(d0 + ARR_B + 16,    srcXl + g + 16);
        } else {
            uint4 z = make_uint4(0u, 0u, 0u, 0u);
            *(uint4*)(dsm + buf * BUF_B + soff)              = z;
            *(uint4*)(dsm + buf * BUF_B + soff + 16)         = z;
            *(uint4*)(dsm + buf * BUF_B + ARR_B + soff)      = z;
            *(uint4*)(dsm + buf * BUF_B + ARR_B + soff + 16) = z;
        }
        CP16(d0 + 2 * ARR_B,      srcWh + g);
        CP16(d0 + 2 * ARR_B + 16, srcWh + g + 16);
        CP16(d0 + 3 * ARR_B,      srcWl + g);
        CP16(d0 + 3 * ARR_B + 16, srcWl + g + 16);
    };

    issue(0, 0);
    CP_COMMIT();

    for (int c = 0; c < 8; c++) {
        if (c < 7) {            // prefetch next chunk into alternate buffer
            issue(c + 1, (c + 1) & 1);
            CP_COMMIT();
            asm volatile("cp.async.wait_group 1;" ::: "memory");
        } else {
            asm volatile("cp.async.wait_group 0;" ::: "memory");
        }
        __syncthreads();

        const uint32_t cur = dbase + (uint32_t)((c & 1) * BUF_B);
        const uint32_t aHi = cur,            aLo = cur + ARR_B;
        const uint32_t bHi = cur + 2*ARR_B,  bLo = cur + 3*ARR_B;

#pragma unroll
        for (int ks = 0; ks < 2; ks++) {
            const uint32_t kb = (uint32_t)(ks * 16 * 2);
            uint32_t bh[4][2], bl[4][2];
#pragma unroll
            for (int p = 0; p < 2; p++) {
                uint32_t addr = bLaneOff + (uint32_t)(p * 16 * PADK * 2) + kb;
                uint32_t r0, r1, r2, r3;
                ldmx4(r0, r1, r2, r3, bHi + addr);
                bh[2*p][0] = r0; bh[2*p][1] = r1;
                bh[2*p+1][0] = r2; bh[2*p+1][1] = r3;
                ldmx4(r0, r1, r2, r3, bLo + addr);
                bl[2*p][0] = r0; bl[2*p][1] = r1;
                bl[2*p+1][0] = r2; bl[2*p+1][1] = r3;
            }
#pragma unroll
            for (int mt = 0; mt < 4; mt++) {
                uint32_t addr = aLaneOff + (uint32_t)(mt * 16 * PADK * 2) + kb;
                uint32_t ah[4], al[4];
                ldmx4(ah[0], ah[1], ah[2], ah[3], aHi + addr);
                ldmx4(al[0], al[1], al[2], al[3], aLo + addr);
#pragma unroll
                for (int nt = 0; nt < 4; nt++) {
                    mma_bf16(acc[mt][nt], ah, bh[nt][0], bh[nt][1]); // hi*hi
                    mma_bf16(acc[mt][nt], ah, bl[nt][0], bl[nt][1]); // hi*lo
                    mma_bf16(acc[mt][nt], al, bh[nt][0], bh[nt][1]); // lo*hi
                }
            }
        }
        __syncthreads();
    }

    const int r0 = blockRow + wm * 64 + (lane >> 2);
    const int c0 = wn * 32 + 2 * (lane & 3);
#pragma unroll
    for (int mt = 0; mt < 4; mt++) {
#pragma unroll
        for (int nt = 0; nt < 4; nt++) {
            int rA = r0 + mt * 16;
            int cc = c0 + nt * 8;
            if (rA < N_NODES)
                *(__half2*)&g_h1[(size_t)rA * H1 + cc] =
                    __floats2half2_rn(acc[mt][nt][0], acc[mt][nt][1]);
            if (rA + 8 < N_NODES)
                *(__half2*)&g_h1[(size_t)(rA + 8) * H1 + cc] =
                    __floats2half2_rn(acc[mt][nt][2], acc[mt][nt][3]);
        }
    }
}

// ---------------- agg1 + warp-local fused GEMM2 -----------------------------
__global__ __launch_bounds__(256) void k_agg1(const float* __restrict__ b1,
                                              const float* __restrict__ W2) {
    __shared__ float sW2t[16][132];   // [c][k], padded
    __shared__ float sa1[8][128];     // warp-private a1 row
    const int tid = threadIdx.x, wid = tid >> 5, lane = tid & 31;

#pragma unroll
    for (int t = 0; t < 8; t++) {
        int i = tid + t * 256;                 // i = k*16 + c
        sW2t[i & 15][i >> 4] = W2[i];
    }
    __syncthreads();

    const float4 bv = ((const float4*)b1)[lane];
    const int cc = lane & 15, hh = lane >> 4;
    const uint2* h = (const uint2*)g_h1;

#pragma unroll 1
    for (int i = 0; i < 8; i++) {
        int n = blockIdx.x * 64 + wid * 8 + i;
        if (n >= N_NODES) break;
        int s0 = g_rowptr[n], s1 = g_rowptr[n + 1];
        float4 acc = bv;
        int e = s0;
        for (; e + 3 < s1; e += 4) {
            int2 E0 = g_edge[e],     E1 = g_edge[e + 1];
            int2 E2 = g_edge[e + 2], E3 = g_edge[e + 3];
            uint2 u0 = h[(size_t)E0.x * 32 + lane];
            uint2 u1 = h[(size_t)E1.x * 32 + lane];
            uint2 u2 = h[(size_t)E2.x * 32 + lane];
            uint2 u3 = h[(size_t)E3.x * 32 + lane];
            float w0 = __int_as_float(E0.y), w1 = __int_as_float(E1.y);
            float w2 = __int_as_float(E2.y), w3 = __int_as_float(E3.y);
            float2 p0 = __half22float2(*(__half2*)&u0.x), q0 = __half22float2(*(__half2*)&u0.y);
            float2 p1 = __half22float2(*(__half2*)&u1.x), q1 = __half22float2(*(__half2*)&u1.y);
            float2 p2 = __half22float2(*(__half2*)&u2.x), q2 = __half22float2(*(__half2*)&u2.y);
            float2 p3 = __half22float2(*(__half2*)&u3.x), q3 = __half22float2(*(__half2*)&u3.y);
            acc.x += w0 * p0.x + w1 * p1.x + w2 * p2.x + w3 * p3.x;
            acc.y += w0 * p0.y + w1 * p1.y + w2 * p2.y + w3 * p3.y;
            acc.z += w0 * q0.x + w1 * q1.x + w2 * q2.x + w3 * q3.x;
            acc.w += w0 * q0.y + w1 * q1.y + w2 * q2.y + w3 * q3.y;
        }
        for (; e < s1; e++) {
            int2 E = g_edge[e];
            float w = __int_as_float(E.y);
            uint2 u = h[(size_t)E.x * 32 + lane];
            float2 p = __half22float2(*(__half2*)&u.x);
            float2 q = __half22float2(*(__half2*)&u.y);
            acc.x += w * p.x; acc.y += w * p.y;
            acc.z += w * q.x; acc.w += w * q.y;
        }
        acc.x = LEAKY(acc.x); acc.y = LEAKY(acc.y);
        acc.z = LEAKY(acc.z); acc.w = LEAKY(acc.w);

        *(float4*)&sa1[wid][lane * 4] = acc;
        __syncwarp();
        const float* ap = &sa1[wid][hh * 64];
        const float* wp = &sW2t[cc][hh * 64];
        float partial = 0.f;
#pragma unroll
        for (int k4 = 0; k4 < 16; k4++) {
            float4 a = *(const float4*)(ap + k4 * 4);
            float4 w = *(const float4*)(wp + k4 * 4);
            partial += a.x * w.x + a.y * w.y + a.z * w.z + a.w * w.w;
        }
        partial += __shfl_xor_sync(0xFFFFFFFFu, partial, 16);
        if (lane < 16) g_h2[(size_t)n * H2 + cc] = __float2half_rn(partial);
        __syncwarp();
    }
}

// ---------------- Aggregation layer 2 (dim 16, fp16): 8 thr/node -----------
__global__ __launch_bounds__(256) void k_agg2(const float* __restrict__ b2) {
    int n = blockIdx.x * 32 + (threadIdx.x >> 3);
    int f2 = threadIdx.x & 7;
    if (n >= N_NODES) return;
    int s0 = g_rowptr[n], s1 = g_rowptr[n + 1];
    float accx = b2[f2 * 2], accy = b2[f2 * 2 + 1];
    const __half2* h = (const __half2*)g_h2;
    int e = s0;
    for (; e + 3 < s1; e += 4) {
        int2 E0 = g_edge[e],     E1 = g_edge[e + 1];
        int2 E2 = g_edge[e + 2], E3 = g_edge[e + 3];
        float w0 = __int_as_float(E0.y), w1 = __int_as_float(E1.y);
        float w2 = __int_as_float(E2.y), w3 = __int_as_float(E3.y);
        float2 v0 = __half22float2(h[(size_t)E0.x * 8 + f2]);
        float2 v1 = __half22float2(h[(size_t)E1.x * 8 + f2]);
        float2 v2 = __half22float2(h[(size_t)E2.x * 8 + f2]);
        float2 v3 = __half22float2(h[(size_t)E3.x * 8 + f2]);
        accx += w0 * v0.x + w1 * v1.x + w2 * v2.x + w3 * v3.x;
        accy += w0 * v0.y + w1 * v1.y + w2 * v2.y + w3 * v3.y;
    }
    for (; e < s1; e++) {
        int2 E = g_edge[e];
        float w = __int_as_float(E.y);
        float2 v = __half22float2(h[(size_t)E.x * 8 + f2]);
        accx += w * v.x; accy += w * v.y;
    }
    accx = LEAKY(accx); accy = LEAKY(accy);
    ((__half2*)g_a2)[(size_t)n * 8 + f2] = __floats2half2_rn(accx, accy);
}

// ---------------- Aggregation layer 3 (dim 16, fp16 gather) ----------------
__global__ __launch_bounds__(256) void k_agg3g() {
    int n = blockIdx.x * 32 + (threadIdx.x >> 3);
    int f2 = threadIdx.x & 7;
    if (n >= N_NODES) return;
    int s0 = g_rowptr[n], s1 = g_rowptr[n + 1];
    float accx = 0.f, accy = 0.f;
    const __half2* h = (const __half2*)g_a2;
    int e = s0;
    for (; e + 3 < s1; e += 4) {
        int2 E0 = g_edge[e],     E1 = g_edge[e + 1];
        int2 E2 = g_edge[e + 2], E3 = g_edge[e + 3];
        float w0 = __int_as_float(E0.y), w1 = __int_as_float(E1.y);
        float w2 = __int_as_float(E2.y), w3 = __int_as_float(E3.y);
        float2 v0 = __half22float2(h[(size_t)E0.x * 8 + f2]);
        float2 v1 = __half22float2(h[(size_t)E1.x * 8 + f2]);
        float2 v2 = __half22float2(h[(size_t)E2.x * 8 + f2]);
        float2 v3 = __half22float2(h[(size_t)E3.x * 8 + f2]);
        accx += w0 * v0.x + w1 * v1.x + w2 * v2.x + w3 * v3.x;
        accy += w0 * v0.y + w1 * v1.y + w2 * v2.y + w3 * v3.y;
    }
    for (; e < s1; e++) {
        int2 E = g_edge[e];
        float w = __int_as_float(E.y);
        float2 v = __half22float2(h[(size_t)E.x * 8 + f2]);
        accx += w * v.x; accy += w * v.y;
    }
    g_g3[(size_t)n * H2 + f2 * 2]     = accx;
    g_g3[(size_t)n * H2 + f2 * 2 + 1] = accy;
}

// ---------------- GEMM3: out = g3 @ W3 + b3  (K=16, N=40) ------------------
__global__ __launch_bounds__(256) void k_gemm3(const float* __restrict__ W,
                                               const float* __restrict__ b3,
                                               float* __restrict__ out) {
    __shared__ float Ws[16 * 40];
    __shared__ float Bs[40];
    __shared__ float Xs[64][17];
    const int rbase = blockIdx.x * 64;
    const int tid = threadIdx.x;
    for (int i = tid; i < 16 * 40; i += 256) Ws[i] = W[i];
    if (tid < 40) Bs[tid] = b3[tid];
#pragma unroll
    for (int t = 0; t < 4; t++) {
        int f = tid + t * 256;
        int row = f >> 4;
        int col = f & 15;
        Xs[row][col] = (rbase + row < N_NODES)
                       ? g_g3[(size_t)(rbase + row) * H2 + col] : 0.f;
    }
    __syncthreads();
#pragma unroll
    for (int t = 0; t < 10; t++) {
        int o = tid + t * 256;
        int r = o / C_OUT;
        int c = o % C_OUT;
        float acc = Bs[c];
#pragma unroll
        for (int k = 0; k < 16; k++) acc += Xs[r][k] * Ws[k * C_OUT + c];
        if (rbase + r < N_NODES)
            out[(size_t)(rbase + r) * C_OUT + c] = acc;
    }
}

// ---------------- launch ----------------------------------------------------
extern "C" void kernel_launch(void* const* d_in, const int* in_sizes, int n_in,
                              void* d_out, int out_size) {
    const float* x  = (const float*)d_in[0];
    const int*   ei = (const int*)d_in[1];     // int32 (JAX x64 disabled)
    const float* W1 = (const float*)d_in[2];
    const float* b1 = (const float*)d_in[3];
    const float* W2 = (const float*)d_in[4];
    const float* b2 = (const float*)d_in[5];
    const float* W3 = (const float*)d_in[6];
    const float* b3 = (const float*)d_in[7];
    float* out = (float*)d_out;

    static cudaStream_t s2 = nullptr;
    static cudaEvent_t evFork = nullptr, evJoin = nullptr;
    if (s2 == nullptr) {
        cudaStreamCreateWithFlags(&s2, cudaStreamNonBlocking);
        cudaEventCreateWithFlags(&evFork, cudaEventDisableTiming);
        cudaEventCreateWithFlags(&evJoin, cudaEventDisableTiming);
        cudaFuncSetAttribute(k_gemm1, cudaFuncAttributeMaxDynamicSharedMemorySize,
                             SMEM_G1);
    }

    const int TB = 256;
    const int gN = NBLK_N;                       // 391
    const int gE = (E_EDGES + TB - 1) / TB;      // 12500
    const int gX = (N_NODES * F_IN / 4 + TB - 1) / TB;   // 25000

    // fork: prep + GEMM1 on side stream; CSR build on main stream.
    cudaEventRecord(evFork, 0);
    cudaStreamWaitEvent(s2, evFork, 0);
    k_prepw<<<(F_IN * H1 + TB - 1) / TB, TB, 0, s2>>>(W1);   // submit 1
    k_prepx<<<gX, TB, 0, s2>>>(x);                            // submit 2

    k_hist<<<gE, TB>>>(ei);                                   // submit 3

    k_gemm1<<<(N_NODES + 127) / 128, 256, SMEM_G1, s2>>>();   // submit 4 (profiled)
    cudaEventRecord(evJoin, s2);

    k_scan_block<<<gN, TB>>>();                               // submit 5
    k_scan_sums<<<1, 512>>>(gN);                              // submit 6
    k_scan_fixup<<<gN, TB>>>();                               // submit 7
    k_fill_edge<<<gE, TB>>>(ei);                              // submit 8

    // join: aggregation needs both CSR and h1
    cudaStreamWaitEvent(0, evJoin, 0);

    k_agg1<<<(N_NODES + 63) / 64, 256>>>(b1, W2);   // fused agg1 + gemm2
    k_agg2<<<(N_NODES + 31) / 32, 256>>>(b2);
    k_agg3g<<<(N_NODES + 31) / 32, 256>>>();
    k_gemm3<<<(N_NODES + 63) / 64, 256>>>(W3, b3, out);
}

// round 16
// speedup vs baseline: 1.0427x; 1.0427x over previous
#include <cuda_runtime.h>
#include <cuda_bf16.h>
#include <cuda_fp16.h>
#include <math.h>
#include <stdint.h>

#define N_NODES 100000
#define F_IN    256
#define H1      128
#define H2      16
#define C_OUT   40
#define E_EDGES 3200000
#define E_TOT   (E_EDGES + N_NODES)
#define NBLK_N  ((N_NODES + 255) / 256)   // 391

// ---------------- scratch (static device arrays; no runtime alloc) ---------
__device__ __align__(16) __half g_h1[N_NODES * H1];     // x @ W1 (fp16)
__device__ __align__(16) __half g_h2[N_NODES * H2];     // fused agg1+gemm2 out
__device__ __align__(16) __half g_a2[N_NODES * H2];     // leaky(agg(h2)+b2) fp16
__device__ __align__(16) float  g_g3[N_NODES * H2];     // agg(a2) fp32
__device__ __align__(16) __nv_bfloat16 g_wt_hi[H1 * F_IN];  // W1^T hi [n][k]
__device__ __align__(16) __nv_bfloat16 g_wt_lo[H1 * F_IN];  // W1^T lo [n][k]
__device__ int   g_deg[N_NODES];          // zero at entry; hist adds; scan resets
__device__ float g_dis[N_NODES];          // deg^{-1/2}
__device__ int   g_rowptr[N_NODES + 1];
__device__ int   g_cursor[N_NODES];
__device__ __align__(8) int2 g_edge[E_TOT];   // (src, wgt-bits) per CSR slot
__device__ int   g_bsums[512];
__device__ int   g_boff[512];

#define LEAKY(v) ((v) > 0.f ? (v) : 0.2f * (v))

// ===================== portable tensor-core helpers (sm_80+) ================
__device__ __forceinline__ uint32_t smem_u32(const void* p) {
    uint32_t a;
    asm("{ .reg .u64 t; cvta.to.shared.u64 t, %1; cvt.u32.u64 %0, t; }"
        : "=r"(a) : "l"(p));
    return a;
}
__device__ __forceinline__ void ldmx4(uint32_t& r0, uint32_t& r1,
                                      uint32_t& r2, uint32_t& r3, uint32_t a) {
    asm volatile("ldmatrix.sync.aligned.m8n8.x4.shared.b16 {%0,%1,%2,%3}, [%4];"
                 : "=r"(r0), "=r"(r1), "=r"(r2), "=r"(r3) : "r"(a));
}
__device__ __forceinline__ void mma_bf16(float* d, const uint32_t* a,
                                         uint32_t b0, uint32_t b1) {
    asm volatile(
        "mma.sync.aligned.m16n8k16.row.col.f32.bf16.bf16.f32 "
        "{%0,%1,%2,%3}, {%4,%5,%6,%7}, {%8,%9}, {%0,%1,%2,%3};"
        : "+f"(d[0]), "+f"(d[1]), "+f"(d[2]), "+f"(d[3])
        : "r"(a[0]), "r"(a[1]), "r"(a[2]), "r"(a[3]), "r"(b0), "r"(b1));
}
#define CP16(dst, src) \
    asm volatile("cp.async.cg.shared.global [%0], [%1], 16;" \
                 :: "r"(dst), "l"(src) : "memory")
#define CP_COMMIT() asm volatile("cp.async.commit_group;" ::: "memory")

// ---------------- W1 transpose + bf16 split ---------------------------------
__global__ void k_prepw(const float* __restrict__ W1) {
    int i = blockIdx.x * blockDim.x + threadIdx.x;
    if (i < F_IN * H1) {
        int k = i >> 7, n = i & 127;
        float w = W1[i];
        __nv_bfloat16 hi = __float2bfloat16_rn(w);
        float lo = w - __bfloat162float(hi);
        g_wt_hi[n * F_IN + k] = hi;
        g_wt_lo[n * F_IN + k] = __float2bfloat16_rn(lo);
    }
}

// ---------------- CSR: histogram (g_deg starts at 0) ------------------------
__global__ void k_hist(const int* __restrict__ ei) {
    int e = blockIdx.x * blockDim.x + threadIdx.x;
    if (e < E_EDGES) atomicAdd(&g_deg[ei[E_EDGES + e]], 1);
}

// ---------------- CSR: hierarchical scan ------------------------------------
__global__ void k_scan_block() {
    __shared__ int s[256];
    int b = blockIdx.x, t = threadIdx.x;
    int i = b * 256 + t;
    int v = 0;
    if (i < N_NODES) {
        v = g_deg[i] + 1;                 // +1 self loop
        g_deg[i] = 0;                     // reset for next graph replay
        g_dis[i] = rsqrtf((float)v);
    }
    s[t] = v;
    __syncthreads();
#pragma unroll
    for (int off = 1; off < 256; off <<= 1) {
        int add = (t >= off) ? s[t - off] : 0;
        __syncthreads();
        s[t] += add;
        __syncthreads();
    }
    int incl = s[t];
    if (i < N_NODES) g_rowptr[i] = incl - v;
    if (t == 255) g_bsums[b] = incl;
}
__global__ void k_scan_sums(int nblk) {
    __shared__ int s[512];
    int t = threadIdx.x;
    int v = (t < nblk) ? g_bsums[t] : 0;
    s[t] = v;
    __syncthreads();
#pragma unroll
    for (int off = 1; off < 512; off <<= 1) {
        int add = (t >= off) ? s[t - off] : 0;
        __syncthreads();
        s[t] += add;
        __syncthreads();
    }
    int incl = s[t];
    if (t < nblk) g_boff[t] = incl - v;
    if (t == 511) g_rowptr[N_NODES] = incl;
}
__global__ void k_scan_fixup() {
    int i = blockIdx.x * blockDim.x + threadIdx.x;
    if (i < N_NODES) {
        int v = g_rowptr[i] + g_boff[i >> 8];
        g_rowptr[i] = v;
        g_cursor[i] = v + 1;
        float d = g_dis[i];
        g_edge[v] = make_int2(i, __float_as_int(d * d));
    }
}
__global__ void k_fill_edge(const int* __restrict__ ei) {
    int e = blockIdx.x * blockDim.x + threadIdx.x;
    if (e < E_EDGES) {
        int s = ei[e];
        int d = ei[E_EDGES + e];
        int p = atomicAdd(&g_cursor[d], 1);
        float w = g_dis[s] * g_dis[d];
        g_edge[p] = make_int2(s, __float_as_int(w));
    }
}

// ---------------- GEMM1: h1 = X @ W1 ----------------------------------------
// cp.async double-buffer: Xf32 (16KB/buf) + W hi/lo bf16 (2x10KB/buf).
// X converted smem(fp32)->smem(bf16 hi/lo) in-kernel; A arrays single-buffered.
#define PADK   40
#define ARR_B  10240                      // 128 rows * 80 B (PADK bf16)
#define XF_B   16384                      // 128 rows * 128 B fp32
// offsets in dynamic smem:
#define OFF_XF0  0
#define OFF_XF1  16384
#define OFF_AHI  32768
#define OFF_ALO  43008
#define OFF_B0   53248                    // BHI0, BLO0
#define OFF_B1   73728                    // BHI1, BLO1
#define SMEM_G1  94208
__global__ __launch_bounds__(256, 2) void k_gemm1(const float* __restrict__ X) {
    extern __shared__ char dsm[];
    const uint32_t dbase = smem_u32(dsm);

    const int tid = threadIdx.x, wid = tid >> 5, lane = tid & 31;
    const int wm = wid & 1, wn = wid >> 1;
    const int blockRow = blockIdx.x * 128;

    const int srow = tid >> 1;          // 0..127
    const int skh  = tid & 1;           // half of the per-chunk row segment
    const int grow = blockRow + srow;
    const bool rowOK = (grow < N_NODES);

    const uint32_t aLaneOff =
        (uint32_t)((wm * 64 + (lane & 15)) * PADK + (lane >> 4) * 8) * 2;
    const uint32_t bLaneOff =
        (uint32_t)((wn * 32 + (lane & 7) + (lane >> 4) * 8) * PADK +
                   ((lane >> 3) & 1) * 8) * 2;

    float acc[4][4][4];
#pragma unroll
    for (int i = 0; i < 4; i++)
#pragma unroll
        for (int j = 0; j < 4; j++)
#pragma unroll
            for (int q = 0; q < 4; q++) acc[i][j][q] = 0.f;

    const char* srcX  = (const char*)(X + (size_t)grow * F_IN) + skh * 64;
    const char* srcWh = (const char*)g_wt_hi + (size_t)srow * 512 + skh * 32;
    const char* srcWl = (const char*)g_wt_lo + (size_t)srow * 512 + skh * 32;

    // per-chunk cp.async issue: Xf32 (128 B/row) + W hi/lo (64 B/row each)
    auto issue = [&](int c, int buf) {
        // X: this thread covers row srow, bytes [skh*64, skh*64+64) of the 128
        uint32_t xd = dbase + (uint32_t)(buf ? OFF_XF1 : OFF_XF0) +
                      (uint32_t)(srow * 128 + skh * 64);
        if (rowOK) {
            const char* sx = srcX + c * 128;
            CP16(xd,      sx);
            CP16(xd + 16, sx + 16);
            CP16(xd + 32, sx + 32);
            CP16(xd + 48, sx + 48);
        } else {
            uint4 z = make_uint4(0u, 0u, 0u, 0u);
            char* p = dsm + (buf ? OFF_XF1 : OFF_XF0) + srow * 128 + skh * 64;
            *(uint4*)(p)      = z;
            *(uint4*)(p + 16) = z;
            *(uint4*)(p + 32) = z;
            *(uint4*)(p + 48) = z;
        }
        uint32_t bd = dbase + (uint32_t)(buf ? OFF_B1 : OFF_B0) +
                      (uint32_t)(srow * 80 + skh * 32);
        const char* wh = srcWh + c * 64;
        const char* wl = srcWl + c * 64;
        CP16(bd,                 wh);
        CP16(bd + 16,            wh + 16);
        CP16(bd + ARR_B,         wl);
        CP16(bd + ARR_B + 16,    wl + 16);
    };

    issue(0, 0);
    CP_COMMIT();

    for (int c = 0; c < 8; c++) {
        const int buf = c & 1;
        // wait for chunk c's data (all issued groups, since the only pending
        // group at this point is chunk c's)
        asm volatile("cp.async.wait_group 0;" ::: "memory");
        __syncthreads();

        // ---- convert Xf32[buf] -> Ahi/Alo (single-buffered) ----
        {
            const char* xf = dsm + (buf ? OFF_XF1 : OFF_XF0);
#pragma unroll
            for (int j = 0; j < 4; j++) {
                int fidx = j * 256 + tid;          // float4 index 0..1023
                int row  = fidx >> 3;              // 8 float4 per 32-f row
                int col  = (fidx & 7) * 4;
                float4 v = *(const float4*)(xf + fidx * 16);
                float f[4] = {v.x, v.y, v.z, v.w};
                unsigned short hb[4], lb[4];
#pragma unroll
                for (int q = 0; q < 4; q++) {
                    __nv_bfloat16 h = __float2bfloat16_rn(f[q]);
                    __nv_bfloat16 l = __float2bfloat16_rn(f[q] - __bfloat162float(h));
                    hb[q] = *(unsigned short*)&h;
                    lb[q] = *(unsigned short*)&l;
                }
                uint2 ph = make_uint2((uint32_t)hb[0] | ((uint32_t)hb[1] << 16),
                                      (uint32_t)hb[2] | ((uint32_t)hb[3] << 16));
                uint2 pl = make_uint2((uint32_t)lb[0] | ((uint32_t)lb[1] << 16),
                                      (uint32_t)lb[2] | ((uint32_t)lb[3] << 16));
                uint32_t ao = (uint32_t)(row * 80 + col * 2);
                *(uint2*)(dsm + OFF_AHI + ao) = ph;
                *(uint2*)(dsm + OFF_ALO + ao) = pl;
            }
        }
        // prefetch next chunk into the other buffer (overlaps MMAs below)
        if (c < 7) {
            issue(c + 1, buf ^ 1);
            CP_COMMIT();
        }
        __syncthreads();

        const uint32_t aHi = dbase + OFF_AHI, aLo = dbase + OFF_ALO;
        const uint32_t bHi = dbase + (uint32_t)(buf ? OFF_B1 : OFF_B0);
        const uint32_t bLo = bHi + ARR_B;

#pragma unroll
        for (int ks = 0; ks < 2; ks++) {
            const uint32_t kb = (uint32_t)(ks * 16 * 2);
            uint32_t bh[4][2], bl[4][2];
#pragma unroll
            for (int p = 0; p < 2; p++) {
                uint32_t addr = bLaneOff + (uint32_t)(p * 16 * PADK * 2) + kb;
                uint32_t r0, r1, r2, r3;
                ldmx4(r0, r1, r2, r3, bHi + addr);
                bh[2*p][0] = r0; bh[2*p][1] = r1;
                bh[2*p+1][0] = r2; bh[2*p+1][1] = r3;
                ldmx4(r0, r1, r2, r3, bLo + addr);
                bl[2*p][0] = r0; bl[2*p][1] = r1;
                bl[2*p+1][0] = r2; bl[2*p+1][1] = r3;
            }
#pragma unroll
            for (int mt = 0; mt < 4; mt++) {
                uint32_t addr = aLaneOff + (uint32_t)(mt * 16 * PADK * 2) + kb;
                uint32_t ah[4], al[4];
                ldmx4(ah[0], ah[1], ah[2], ah[3], aHi + addr);
                ldmx4(al[0], al[1], al[2], al[3], aLo + addr);
#pragma unroll
                for (int nt = 0; nt < 4; nt++) {
                    mma_bf16(acc[mt][nt], ah, bh[nt][0], bh[nt][1]); // hi*hi
                    mma_bf16(acc[mt][nt], ah, bl[nt][0], bl[nt][1]); // hi*lo
                    mma_bf16(acc[mt][nt], al, bh[nt][0], bh[nt][1]); // lo*hi
                }
            }
        }
        __syncthreads();   // MMAs done before next conversion overwrites A
    }

    const int r0 = blockRow + wm * 64 + (lane >> 2);
    const int c0 = wn * 32 + 2 * (lane & 3);
#pragma unroll
    for (int mt = 0; mt < 4; mt++) {
#pragma unroll
        for (int nt = 0; nt < 4; nt++) {
            int rA = r0 + mt * 16;
            int cc = c0 + nt * 8;
            if (rA < N_NODES)
                *(__half2*)&g_h1[(size_t)rA * H1 + cc] =
                    __floats2half2_rn(acc[mt][nt][0], acc[mt][nt][1]);
            if (rA + 8 < N_NODES)
                *(__half2*)&g_h1[(size_t)(rA + 8) * H1 + cc] =
                    __floats2half2_rn(acc[mt][nt][2], acc[mt][nt][3]);
        }
    }
}

// ---------------- agg1 + warp-local fused GEMM2 -----------------------------
__global__ __launch_bounds__(256) void k_agg1(const float* __restrict__ b1,
                                              const float* __restrict__ W2) {
    __shared__ float sW2t[16][132];
    __shared__ float sa1[8][128];
    const int tid = threadIdx.x, wid = tid >> 5, lane = tid & 31;

#pragma unroll
    for (int t = 0; t < 8; t++) {
        int i = tid + t * 256;
        sW2t[i & 15][i >> 4] = W2[i];
    }
    __syncthreads();

    const float4 bv = ((const float4*)b1)[lane];
    const int cc = lane & 15, hh = lane >> 4;
    const uint2* h = (const uint2*)g_h1;

#pragma unroll 1
    for (int i = 0; i < 8; i++) {
        int n = blockIdx.x * 64 + wid * 8 + i;
        if (n >= N_NODES) break;
        int s0 = g_rowptr[n], s1 = g_rowptr[n + 1];
        float4 acc = bv;
        int e = s0;
        for (; e + 3 < s1; e += 4) {
            int2 E0 = g_edge[e],     E1 = g_edge[e + 1];
            int2 E2 = g_edge[e + 2], E3 = g_edge[e + 3];
            uint2 u0 = h[(size_t)E0.x * 32 + lane];
            uint2 u1 = h[(size_t)E1.x * 32 + lane];
            uint2 u2 = h[(size_t)E2.x * 32 + lane];
            uint2 u3 = h[(size_t)E3.x * 32 + lane];
            float w0 = __int_as_float(E0.y), w1 = __int_as_float(E1.y);
            float w2 = __int_as_float(E2.y), w3 = __int_as_float(E3.y);
            float2 p0 = __half22float2(*(__half2*)&u0.x), q0 = __half22float2(*(__half2*)&u0.y);
            float2 p1 = __half22float2(*(__half2*)&u1.x), q1 = __half22float2(*(__half2*)&u1.y);
            float2 p2 = __half22float2(*(__half2*)&u2.x), q2 = __half22float2(*(__half2*)&u2.y);
            float2 p3 = __half22float2(*(__half2*)&u3.x), q3 = __half22float2(*(__half2*)&u3.y);
            acc.x += w0 * p0.x + w1 * p1.x + w2 * p2.x + w3 * p3.x;
            acc.y += w0 * p0.y + w1 * p1.y + w2 * p2.y + w3 * p3.y;
            acc.z += w0 * q0.x + w1 * q1.x + w2 * q2.x + w3 * q3.x;
            acc.w += w0 * q0.y + w1 * q1.y + w2 * q2.y + w3 * q3.y;
        }
        for (; e < s1; e++) {
            int2 E = g_edge[e];
            float w = __int_as_float(E.y);
            uint2 u = h[(size_t)E.x * 32 + lane];
            float2 p = __half22float2(*(__half2*)&u.x);
            float2 q = __half22float2(*(__half2*)&u.y);
            acc.x += w * p.x; acc.y += w * p.y;
            acc.z += w * q.x; acc.w += w * q.y;
        }
        acc.x = LEAKY(acc.x); acc.y = LEAKY(acc.y);
        acc.z = LEAKY(acc.z); acc.w = LEAKY(acc.w);

        *(float4*)&sa1[wid][lane * 4] = acc;
        __syncwarp();
        const float* ap = &sa1[wid][hh * 64];
        const float* wp = &sW2t[cc][hh * 64];
        float partial = 0.f;
#pragma unroll
        for (int k4 = 0; k4 < 16; k4++) {
            float4 a = *(const float4*)(ap + k4 * 4);
            float4 w = *(const float4*)(wp + k4 * 4);
            partial += a.x * w.x + a.y * w.y + a.z * w.z + a.w * w.w;
        }
        partial += __shfl_xor_sync(0xFFFFFFFFu, partial, 16);
        if (lane < 16) g_h2[(size_t)n * H2 + cc] = __float2half_rn(partial);
        __syncwarp();
    }
}

// ---------------- Aggregation layer 2 (dim 16, fp16): 8 thr/node -----------
__global__ __launch_bounds__(256) void k_agg2(const float* __restrict__ b2) {
    int n = blockIdx.x * 32 + (threadIdx.x >> 3);
    int f2 = threadIdx.x & 7;
    if (n >= N_NODES) return;
    int s0 = g_rowptr[n], s1 = g_rowptr[n + 1];
    float accx = b2[f2 * 2], accy = b2[f2 * 2 + 1];
    const __half2* h = (const __half2*)g_h2;
    int e = s0;
    for (; e + 3 < s1; e += 4) {
        int2 E0 = g_edge[e],     E1 = g_edge[e + 1];
        int2 E2 = g_edge[e + 2], E3 = g_edge[e + 3];
        float w0 = __int_as_float(E0.y), w1 = __int_as_float(E1.y);
        float w2 = __int_as_float(E2.y), w3 = __int_as_float(E3.y);
        float2 v0 = __half22float2(h[(size_t)E0.x * 8 + f2]);
        float2 v1 = __half22float2(h[(size_t)E1.x * 8 + f2]);
        float2 v2 = __half22float2(h[(size_t)E2.x * 8 + f2]);
        float2 v3 = __half22float2(h[(size_t)E3.x * 8 + f2]);
        accx += w0 * v0.x + w1 * v1.x + w2 * v2.x + w3 * v3.x;
        accy += w0 * v0.y + w1 * v1.y + w2 * v2.y + w3 * v3.y;
    }
    for (; e < s1; e++) {
        int2 E = g_edge[e];
        float w = __int_as_float(E.y);
        float2 v = __half22float2(h[(size_t)E.x * 8 + f2]);
        accx += w * v.x; accy += w * v.y;
    }
    accx = LEAKY(accx); accy = LEAKY(accy);
    ((__half2*)g_a2)[(size_t)n * 8 + f2] = __floats2half2_rn(accx, accy);
}

// ---------------- Aggregation layer 3 (dim 16, fp16 gather) ----------------
__global__ __launch_bounds__(256) void k_agg3g() {
    int n = blockIdx.x * 32 + (threadIdx.x >> 3);
    int f2 = threadIdx.x & 7;
    if (n >= N_NODES) return;
    int s0 = g_rowptr[n], s1 = g_rowptr[n + 1];
    float accx = 0.f, accy = 0.f;
    const __half2* h = (const __half2*)g_a2;
    int e = s0;
    for (; e + 3 < s1; e += 4) {
        int2 E0 = g_edge[e],     E1 = g_edge[e + 1];
        int2 E2 = g_edge[e + 2], E3 = g_edge[e + 3];
        float w0 = __int_as_float(E0.y), w1 = __int_as_float(E1.y);
        float w2 = __int_as_float(E2.y), w3 = __int_as_float(E3.y);
        float2 v0 = __half22float2(h[(size_t)E0.x * 8 + f2]);
        float2 v1 = __half22float2(h[(size_t)E1.x * 8 + f2]);
        float2 v2 = __half22float2(h[(size_t)E2.x * 8 + f2]);
        float2 v3 = __half22float2(h[(size_t)E3.x * 8 + f2]);
        accx += w0 * v0.x + w1 * v1.x + w2 * v2.x + w3 * v3.x;
        accy += w0 * v0.y + w1 * v1.y + w2 * v2.y + w3 * v3.y;
    }
    for (; e < s1; e++) {
        int2 E = g_edge[e];
        float w = __int_as_float(E.y);
        float2 v = __half22float2(h[(size_t)E.x * 8 + f2]);
        accx += w * v.x; accy += w * v.y;
    }
    g_g3[(size_t)n * H2 + f2 * 2]     = accx;
    g_g3[(size_t)n * H2 + f2 * 2 + 1] = accy;
}

// ---------------- GEMM3: out = g3 @ W3 + b3  (K=16, N=40) ------------------
__global__ __launch_bounds__(256) void k_gemm3(const float* __restrict__ W,
                                               const float* __restrict__ b3,
                                               float* __restrict__ out) {
    __shared__ float Ws[16 * 40];
    __shared__ float Bs[40];
    __shared__ float Xs[64][17];
    const int rbase = blockIdx.x * 64;
    const int tid = threadIdx.x;
    for (int i = tid; i < 16 * 40; i += 256) Ws[i] = W[i];
    if (tid < 40) Bs[tid] = b3[tid];
#pragma unroll
    for (int t = 0; t < 4; t++) {
        int f = tid + t * 256;
        int row = f >> 4;
        int col = f & 15;
        Xs[row][col] = (rbase + row < N_NODES)
                       ? g_g3[(size_t)(rbase + row) * H2 + col] : 0.f;
    }
    __syncthreads();
#pragma unroll
    for (int t = 0; t < 10; t++) {
        int o = tid + t * 256;
        int r = o / C_OUT;
        int c = o % C_OUT;
        float acc = Bs[c];
#pragma unroll
        for (int k = 0; k < 16; k++) acc += Xs[r][k] * Ws[k * C_OUT + c];
        if (rbase + r < N_NODES)
            out[(size_t)(rbase + r) * C_OUT + c] = acc;
    }
}

// ---------------- launch (single stream; overlap proved ineffective) -------
extern "C" void kernel_launch(void* const* d_in, const int* in_sizes, int n_in,
                              void* d_out, int out_size) {
    const float* x  = (const float*)d_in[0];
    const int*   ei = (const int*)d_in[1];     // int32 (JAX x64 disabled)
    const float* W1 = (const float*)d_in[2];
    const float* b1 = (const float*)d_in[3];
    const float* W2 = (const float*)d_in[4];
    const float* b2 = (const float*)d_in[5];
    const float* W3 = (const float*)d_in[6];
    const float* b3 = (const float*)d_in[7];
    float* out = (float*)d_out;

    static bool init = false;
    if (!init) {
        init = true;
        cudaFuncSetAttribute(k_gemm1, cudaFuncAttributeMaxDynamicSharedMemorySize,
                             SMEM_G1);
    }

    const int TB = 256;
    const int gN = NBLK_N;                       // 391
    const int gE = (E_EDGES + TB - 1) / TB;      // 12500

    k_prepw<<<(F_IN * H1 + TB - 1) / TB, TB>>>(W1);           // 1
    k_hist<<<gE, TB>>>(ei);                                    // 2
    k_scan_block<<<gN, TB>>>();                                // 3
    k_gemm1<<<(N_NODES + 127) / 128, 256, SMEM_G1>>>(x);       // 4 (profiled)
    k_scan_sums<<<1, 512>>>(gN);                               // 5
    k_scan_fixup<<<gN, TB>>>();                                // 6
    k_fill_edge<<<gE, TB>>>(ei);                               // 7

    k_agg1<<<(N_NODES + 63) / 64, 256>>>(b1, W2);   // fused agg1 + gemm2
    k_agg2<<<(N_NODES + 31) / 32, 256>>>(b2);
    k_agg3g<<<(N_NODES + 31) / 32, 256>>>();
    k_gemm3<<<(N_NODES + 63) / 64, 256>>>(W3, b3, out);
}

// round 17
// speedup vs baseline: 1.0846x; 1.0402x over previous
#include <cuda_runtime.h>
#include <cuda_bf16.h>
#include <cuda_fp16.h>
#include <math.h>
#include <stdint.h>

#define N_NODES 100000
#define F_IN    256
#define H1      128
#define H2      16
#define C_OUT   40
#define E_EDGES 3200000
#define E_TOT   (E_EDGES + N_NODES)
#define NBLK_N  ((N_NODES + 255) / 256)   // 391

// ---------------- scratch (static device arrays; no runtime alloc) ---------
__device__ __align__(16) __half g_h1[N_NODES * H1];     // x @ W1 (fp16)
__device__ __align__(16) __half g_h2[N_NODES * H2];     // fused agg1+gemm2 out
__device__ __align__(16) __half g_a2[N_NODES * H2];     // leaky(agg(h2)+b2) fp16
__device__ __align__(16) float  g_g3[N_NODES * H2];     // agg(a2) fp32
__device__ __align__(16) __nv_bfloat16 g_wt_hi[H1 * F_IN];  // W1^T hi [n][k]
__device__ __align__(16) __nv_bfloat16 g_wt_lo[H1 * F_IN];  // W1^T lo [n][k]
__device__ int   g_deg[N_NODES];          // zero at entry; hist adds; scan resets
__device__ float g_dis[N_NODES];          // deg^{-1/2}
__device__ int   g_rowptr[N_NODES + 1];
__device__ int   g_cursor[N_NODES];
__device__ __align__(8) int2 g_edge[E_TOT];   // (src, wgt-bits) per CSR slot
__device__ int   g_bsums[512];
__device__ int   g_boff[512];

#define LEAKY(v) ((v) > 0.f ? (v) : 0.2f * (v))

// ===================== portable tensor-core helpers (sm_80+) ================
__device__ __forceinline__ uint32_t smem_u32(const void* p) {
    uint32_t a;
    asm("{ .reg .u64 t; cvta.to.shared.u64 t, %1; cvt.u32.u64 %0, t; }"
        : "=r"(a) : "l"(p));
    return a;
}
__device__ __forceinline__ void ldmx4(uint32_t& r0, uint32_t& r1,
                                      uint32_t& r2, uint32_t& r3, uint32_t a) {
    asm volatile("ldmatrix.sync.aligned.m8n8.x4.shared.b16 {%0,%1,%2,%3}, [%4];"
                 : "=r"(r0), "=r"(r1), "=r"(r2), "=r"(r3) : "r"(a));
}
__device__ __forceinline__ void mma_bf16(float* d, const uint32_t* a,
                                         uint32_t b0, uint32_t b1) {
    asm volatile(
        "mma.sync.aligned.m16n8k16.row.col.f32.bf16.bf16.f32 "
        "{%0,%1,%2,%3}, {%4,%5,%6,%7}, {%8,%9}, {%0,%1,%2,%3};"
        : "+f"(d[0]), "+f"(d[1]), "+f"(d[2]), "+f"(d[3])
        : "r"(a[0]), "r"(a[1]), "r"(a[2]), "r"(a[3]), "r"(b0), "r"(b1));
}
#define CP16(dst, src) \
    asm volatile("cp.async.cg.shared.global [%0], [%1], 16;" \
                 :: "r"(dst), "l"(src) : "memory")
#define CP_COMMIT() asm volatile("cp.async.commit_group;" ::: "memory")

// ---------------- W1 transpose + bf16 split ---------------------------------
__global__ void k_prepw(const float* __restrict__ W1) {
    int i = blockIdx.x * blockDim.x + threadIdx.x;
    if (i < F_IN * H1) {
        int k = i >> 7, n = i & 127;
        float w = W1[i];
        __nv_bfloat16 hi = __float2bfloat16_rn(w);
        float lo = w - __bfloat162float(hi);
        g_wt_hi[n * F_IN + k] = hi;
        g_wt_lo[n * F_IN + k] = __float2bfloat16_rn(lo);
    }
}

// ---------------- CSR: histogram (g_deg starts at 0) ------------------------
__global__ void k_hist(const int* __restrict__ ei) {
    int e = blockIdx.x * blockDim.x + threadIdx.x;
    if (e < E_EDGES) atomicAdd(&g_deg[ei[E_EDGES + e]], 1);
}

// ---------------- CSR: hierarchical scan ------------------------------------
__global__ void k_scan_block() {
    __shared__ int s[256];
    int b = blockIdx.x, t = threadIdx.x;
    int i = b * 256 + t;
    int v = 0;
    if (i < N_NODES) {
        v = g_deg[i] + 1;                 // +1 self loop
        g_deg[i] = 0;                     // reset for next graph replay
        g_dis[i] = rsqrtf((float)v);
    }
    s[t] = v;
    __syncthreads();
#pragma unroll
    for (int off = 1; off < 256; off <<= 1) {
        int add = (t >= off) ? s[t - off] : 0;
        __syncthreads();
        s[t] += add;
        __syncthreads();
    }
    int incl = s[t];
    if (i < N_NODES) g_rowptr[i] = incl - v;
    if (t == 255) g_bsums[b] = incl;
}
__global__ void k_scan_sums(int nblk) {
    __shared__ int s[512];
    int t = threadIdx.x;
    int v = (t < nblk) ? g_bsums[t] : 0;
    s[t] = v;
    __syncthreads();
#pragma unroll
    for (int off = 1; off < 512; off <<= 1) {
        int add = (t >= off) ? s[t - off] : 0;
        __syncthreads();
        s[t] += add;
        __syncthreads();
    }
    int incl = s[t];
    if (t < nblk) g_boff[t] = incl - v;
    if (t == 511) g_rowptr[N_NODES] = incl;
}
__global__ void k_scan_fixup() {
    int i = blockIdx.x * blockDim.x + threadIdx.x;
    if (i < N_NODES) {
        int v = g_rowptr[i] + g_boff[i >> 8];
        g_rowptr[i] = v;
        g_cursor[i] = v + 1;
        float d = g_dis[i];
        g_edge[v] = make_int2(i, __float_as_int(d * d));
    }
}
__global__ void k_fill_edge(const int* __restrict__ ei) {
    int e = blockIdx.x * blockDim.x + threadIdx.x;
    if (e < E_EDGES) {
        int s = ei[e];
        int d = ei[E_EDGES + e];
        int p = atomicAdd(&g_cursor[d], 1);
        float w = g_dis[s] * g_dis[d];
        g_edge[p] = make_int2(s, __float_as_int(w));
    }
}

// ---------------- GEMM1: h1 = X @ W1 ----------------------------------------
// cp.async double-buffer: Xf32 (16KB/buf) + W hi/lo bf16 (2x10KB/buf).
// X converted smem(fp32)->smem(bf16 hi/lo) in-kernel; A arrays single-buffered.
#define PADK   40
#define ARR_B  10240                      // 128 rows * 80 B (PADK bf16)
#define XF_B   16384                      // 128 rows * 128 B fp32
#define OFF_XF0  0
#define OFF_XF1  16384
#define OFF_AHI  32768
#define OFF_ALO  43008
#define OFF_B0   53248                    // BHI0, BLO0
#define OFF_B1   73728                    // BHI1, BLO1
#define SMEM_G1  94208
__global__ __launch_bounds__(256, 2) void k_gemm1(const float* __restrict__ X) {
    extern __shared__ char dsm[];
    const uint32_t dbase = smem_u32(dsm);

    const int tid = threadIdx.x, wid = tid >> 5, lane = tid & 31;
    const int wm = wid & 1, wn = wid >> 1;
    const int blockRow = blockIdx.x * 128;

    const int srow = tid >> 1;          // 0..127
    const int skh  = tid & 1;           // half of the per-chunk row segment
    const int grow = blockRow + srow;
    const bool rowOK = (grow < N_NODES);

    const uint32_t aLaneOff =
        (uint32_t)((wm * 64 + (lane & 15)) * PADK + (lane >> 4) * 8) * 2;
    const uint32_t bLaneOff =
        (uint32_t)((wn * 32 + (lane & 7) + (lane >> 4) * 8) * PADK +
                   ((lane >> 3) & 1) * 8) * 2;

    float acc[4][4][4];
#pragma unroll
    for (int i = 0; i < 4; i++)
#pragma unroll
        for (int j = 0; j < 4; j++)
#pragma unroll
            for (int q = 0; q < 4; q++) acc[i][j][q] = 0.f;

    const char* srcX  = (const char*)(X + (size_t)grow * F_IN) + skh * 64;
    const char* srcWh = (const char*)g_wt_hi + (size_t)srow * 512 + skh * 32;
    const char* srcWl = (const char*)g_wt_lo + (size_t)srow * 512 + skh * 32;

    auto issue = [&](int c, int buf) {
        uint32_t xd = dbase + (uint32_t)(buf ? OFF_XF1 : OFF_XF0) +
                      (uint32_t)(srow * 128 + skh * 64);
        if (rowOK) {
            const char* sx = srcX + c * 128;
            CP16(xd,      sx);
            CP16(xd + 16, sx + 16);
            CP16(xd + 32, sx + 32);
            CP16(xd + 48, sx + 48);
        } else {
            uint4 z = make_uint4(0u, 0u, 0u, 0u);
            char* p = dsm + (buf ? OFF_XF1 : OFF_XF0) + srow * 128 + skh * 64;
            *(uint4*)(p)      = z;
            *(uint4*)(p + 16) = z;
            *(uint4*)(p + 32) = z;
            *(uint4*)(p + 48) = z;
        }
        uint32_t bd = dbase + (uint32_t)(buf ? OFF_B1 : OFF_B0) +
                      (uint32_t)(srow * 80 + skh * 32);
        const char* wh = srcWh + c * 64;
        const char* wl = srcWl + c * 64;
        CP16(bd,                 wh);
        CP16(bd + 16,            wh + 16);
        CP16(bd + ARR_B,         wl);
        CP16(bd + ARR_B + 16,    wl + 16);
    };

    issue(0, 0);
    CP_COMMIT();

    for (int c = 0; c < 8; c++) {
        const int buf = c & 1;
        asm volatile("cp.async.wait_group 0;" ::: "memory");
        __syncthreads();

        // ---- convert Xf32[buf] -> Ahi/Alo (single-buffered) ----
        {
            const char* xf = dsm + (buf ? OFF_XF1 : OFF_XF0);
#pragma unroll
            for (int j = 0; j < 4; j++) {
                int fidx = j * 256 + tid;          // float4 index 0..1023
                int row  = fidx >> 3;
                int col  = (fidx & 7) * 4;
                float4 v = *(const float4*)(xf + fidx * 16);
                float f[4] = {v.x, v.y, v.z, v.w};
                unsigned short hb[4], lb[4];
#pragma unroll
                for (int q = 0; q < 4; q++) {
                    __nv_bfloat16 h = __float2bfloat16_rn(f[q]);
                    __nv_bfloat16 l = __float2bfloat16_rn(f[q] - __bfloat162float(h));
                    hb[q] = *(unsigned short*)&h;
                    lb[q] = *(unsigned short*)&l;
                }
                uint2 ph = make_uint2((uint32_t)hb[0] | ((uint32_t)hb[1] << 16),
                                      (uint32_t)hb[2] | ((uint32_t)hb[3] << 16));
                uint2 pl = make_uint2((uint32_t)lb[0] | ((uint32_t)lb[1] << 16),
                                      (uint32_t)lb[2] | ((uint32_t)lb[3] << 16));
                uint32_t ao = (uint32_t)(row * 80 + col * 2);
                *(uint2*)(dsm + OFF_AHI + ao) = ph;
                *(uint2*)(dsm + OFF_ALO + ao) = pl;
            }
        }
        if (c < 7) {
            issue(c + 1, buf ^ 1);
            CP_COMMIT();
        }
        __syncthreads();

        const uint32_t aHi = dbase + OFF_AHI, aLo = dbase + OFF_ALO;
        const uint32_t bHi = dbase + (uint32_t)(buf ? OFF_B1 : OFF_B0);
        const uint32_t bLo = bHi + ARR_B;

#pragma unroll
        for (int ks = 0; ks < 2; ks++) {
            const uint32_t kb = (uint32_t)(ks * 16 * 2);
            uint32_t bh[4][2], bl[4][2];
#pragma unroll
            for (int p = 0; p < 2; p++) {
                uint32_t addr = bLaneOff + (uint32_t)(p * 16 * PADK * 2) + kb;
                uint32_t r0, r1, r2, r3;
                ldmx4(r0, r1, r2, r3, bHi + addr);
                bh[2*p][0] = r0; bh[2*p][1] = r1;
                bh[2*p+1][0] = r2; bh[2*p+1][1] = r3;
                ldmx4(r0, r1, r2, r3, bLo + addr);
                bl[2*p][0] = r0; bl[2*p][1] = r1;
                bl[2*p+1][0] = r2; bl[2*p+1][1] = r3;
            }
#pragma unroll
            for (int mt = 0; mt < 4; mt++) {
                uint32_t addr = aLaneOff + (uint32_t)(mt * 16 * PADK * 2) + kb;
                uint32_t ah[4], al[4];
                ldmx4(ah[0], ah[1], ah[2], ah[3], aHi + addr);
                ldmx4(al[0], al[1], al[2], al[3], aLo + addr);
#pragma unroll
                for (int nt = 0; nt < 4; nt++) {
                    mma_bf16(acc[mt][nt], ah, bh[nt][0], bh[nt][1]); // hi*hi
                    mma_bf16(acc[mt][nt], ah, bl[nt][0], bl[nt][1]); // hi*lo
                    mma_bf16(acc[mt][nt], al, bh[nt][0], bh[nt][1]); // lo*hi
                }
            }
        }
        __syncthreads();   // MMAs done before next conversion overwrites A
    }

    const int r0 = blockRow + wm * 64 + (lane >> 2);
    const int c0 = wn * 32 + 2 * (lane & 3);
#pragma unroll
    for (int mt = 0; mt < 4; mt++) {
#pragma unroll
        for (int nt = 0; nt < 4; nt++) {
            int rA = r0 + mt * 16;
            int cc = c0 + nt * 8;
            if (rA < N_NODES)
                *(__half2*)&g_h1[(size_t)rA * H1 + cc] =
                    __floats2half2_rn(acc[mt][nt][0], acc[mt][nt][1]);
            if (rA + 8 < N_NODES)
                *(__half2*)&g_h1[(size_t)(rA + 8) * H1 + cc] =
                    __floats2half2_rn(acc[mt][nt][2], acc[mt][nt][3]);
        }
    }
}

// ---------------- agg1 + warp-local fused GEMM2 -----------------------------
__global__ __launch_bounds__(256) void k_agg1(const float* __restrict__ b1,
                                              const float* __restrict__ W2) {
    __shared__ float sW2t[16][132];
    __shared__ float sa1[8][128];
    const int tid = threadIdx.x, wid = tid >> 5, lane = tid & 31;

#pragma unroll
    for (int t = 0; t < 8; t++) {
        int i = tid + t * 256;
        sW2t[i & 15][i >> 4] = W2[i];
    }
    __syncthreads();

    const float4 bv = ((const float4*)b1)[lane];
    const int cc = lane & 15, hh = lane >> 4;
    const uint2* h = (const uint2*)g_h1;

#pragma unroll 1
    for (int i = 0; i < 8; i++) {
        int n = blockIdx.x * 64 + wid * 8 + i;
        if (n >= N_NODES) break;
        int s0 = g_rowptr[n], s1 = g_rowptr[n + 1];
        float4 acc = bv;
        int e = s0;
        for (; e + 3 < s1; e += 4) {
            int2 E0 = g_edge[e],     E1 = g_edge[e + 1];
            int2 E2 = g_edge[e + 2], E3 = g_edge[e + 3];
            uint2 u0 = h[(size_t)E0.x * 32 + lane];
            uint2 u1 = h[(size_t)E1.x * 32 + lane];
            uint2 u2 = h[(size_t)E2.x * 32 + lane];
            uint2 u3 = h[(size_t)E3.x * 32 + lane];
            float w0 = __int_as_float(E0.y), w1 = __int_as_float(E1.y);
            float w2 = __int_as_float(E2.y), w3 = __int_as_float(E3.y);
            float2 p0 = __half22float2(*(__half2*)&u0.x), q0 = __half22float2(*(__half2*)&u0.y);
            float2 p1 = __half22float2(*(__half2*)&u1.x), q1 = __half22float2(*(__half2*)&u1.y);
            float2 p2 = __half22float2(*(__half2*)&u2.x), q2 = __half22float2(*(__half2*)&u2.y);
            float2 p3 = __half22float2(*(__half2*)&u3.x), q3 = __half22float2(*(__half2*)&u3.y);
            acc.x += w0 * p0.x + w1 * p1.x + w2 * p2.x + w3 * p3.x;
            acc.y += w0 * p0.y + w1 * p1.y + w2 * p2.y + w3 * p3.y;
            acc.z += w0 * q0.x + w1 * q1.x + w2 * q2.x + w3 * q3.x;
            acc.w += w0 * q0.y + w1 * q1.y + w2 * q2.y + w3 * q3.y;
        }
        for (; e < s1; e++) {
            int2 E = g_edge[e];
            float w = __int_as_float(E.y);
            uint2 u = h[(size_t)E.x * 32 + lane];
            float2 p = __half22float2(*(__half2*)&u.x);
            float2 q = __half22float2(*(__half2*)&u.y);
            acc.x += w * p.x; acc.y += w * p.y;
            acc.z += w * q.x; acc.w += w * q.y;
        }
        acc.x = LEAKY(acc.x); acc.y = LEAKY(acc.y);
        acc.z = LEAKY(acc.z); acc.w = LEAKY(acc.w);

        *(float4*)&sa1[wid][lane * 4] = acc;
        __syncwarp();
        const float* ap = &sa1[wid][hh * 64];
        const float* wp = &sW2t[cc][hh * 64];
        float partial = 0.f;
#pragma unroll
        for (int k4 = 0; k4 < 16; k4++) {
            float4 a = *(const float4*)(ap + k4 * 4);
            float4 w = *(const float4*)(wp + k4 * 4);
            partial += a.x * w.x + a.y * w.y + a.z * w.z + a.w * w.w;
        }
        partial += __shfl_xor_sync(0xFFFFFFFFu, partial, 16);
        if (lane < 16) g_h2[(size_t)n * H2 + cc] = __float2half_rn(partial);
        __syncwarp();
    }
}

// ---------------- Aggregation layer 2 (dim 16, fp16): 8 thr/node -----------
__global__ __launch_bounds__(256) void k_agg2(const float* __restrict__ b2) {
    int n = blockIdx.x * 32 + (threadIdx.x >> 3);
    int f2 = threadIdx.x & 7;
    if (n >= N_NODES) return;
    int s0 = g_rowptr[n], s1 = g_rowptr[n + 1];
    float accx = b2[f2 * 2], accy = b2[f2 * 2 + 1];
    const __half2* h = (const __half2*)g_h2;
    int e = s0;
    for (; e + 3 < s1; e += 4) {
        int2 E0 = g_edge[e],     E1 = g_edge[e + 1];
        int2 E2 = g_edge[e + 2], E3 = g_edge[e + 3];
        float w0 = __int_as_float(E0.y), w1 = __int_as_float(E1.y);
        float w2 = __int_as_float(E2.y), w3 = __int_as_float(E3.y);
        float2 v0 = __half22float2(h[(size_t)E0.x * 8 + f2]);
        float2 v1 = __half22float2(h[(size_t)E1.x * 8 + f2]);
        float2 v2 = __half22float2(h[(size_t)E2.x * 8 + f2]);
        float2 v3 = __half22float2(h[(size_t)E3.x * 8 + f2]);
        accx += w0 * v0.x + w1 * v1.x + w2 * v2.x + w3 * v3.x;
        accy += w0 * v0.y + w1 * v1.y + w2 * v2.y + w3 * v3.y;
    }
    for (; e < s1; e++) {
        int2 E = g_edge[e];
        float w = __int_as_float(E.y);
        float2 v = __half22float2(h[(size_t)E.x * 8 + f2]);
        accx += w * v.x; accy += w * v.y;
    }
    accx = LEAKY(accx); accy = LEAKY(accy);
    ((__half2*)g_a2)[(size_t)n * 8 + f2] = __floats2half2_rn(accx, accy);
}

// ---------------- Aggregation layer 3 (dim 16, fp16 gather) ----------------
__global__ __launch_bounds__(256) void k_agg3g() {
    int n = blockIdx.x * 32 + (threadIdx.x >> 3);
    int f2 = threadIdx.x & 7;
    if (n >= N_NODES) return;
    int s0 = g_rowptr[n], s1 = g_rowptr[n + 1];
    float accx = 0.f, accy = 0.f;
    const __half2* h = (const __half2*)g_a2;
    int e = s0;
    for (; e + 3 < s1; e += 4) {
        int2 E0 = g_edge[e],     E1 = g_edge[e + 1];
        int2 E2 = g_edge[e + 2], E3 = g_edge[e + 3];
        float w0 = __int_as_float(E0.y), w1 = __int_as_float(E1.y);
        float w2 = __int_as_float(E2.y), w3 = __int_as_float(E3.y);
        float2 v0 = __half22float2(h[(size_t)E0.x * 8 + f2]);
        float2 v1 = __half22float2(h[(size_t)E1.x * 8 + f2]);
        float2 v2 = __half22float2(h[(size_t)E2.x * 8 + f2]);
        float2 v3 = __half22float2(h[(size_t)E3.x * 8 + f2]);
        accx += w0 * v0.x + w1 * v1.x + w2 * v2.x + w3 * v3.x;
        accy += w0 * v0.y + w1 * v1.y + w2 * v2.y + w3 * v3.y;
    }
    for (; e < s1; e++) {
        int2 E = g_edge[e];
        float w = __int_as_float(E.y);
        float2 v = __half22float2(h[(size_t)E.x * 8 + f2]);
        accx += w * v.x; accy += w * v.y;
    }
    g_g3[(size_t)n * H2 + f2 * 2]     = accx;
    g_g3[(size_t)n * H2 + f2 * 2 + 1] = accy;
}

// ---------------- GEMM3: out = g3 @ W3 + b3  (K=16, N=40) ------------------
__global__ __launch_bounds__(256) void k_gemm3(const float* __restrict__ W,
                                               const float* __restrict__ b3,
                                               float* __restrict__ out) {
    __shared__ float Ws[16 * 40];
    __shared__ float Bs[40];
    __shared__ float Xs[64][17];
    const int rbase = blockIdx.x * 64;
    const int tid = threadIdx.x;
    for (int i = tid; i < 16 * 40; i += 256) Ws[i] = W[i];
    if (tid < 40) Bs[tid] = b3[tid];
#pragma unroll
    for (int t = 0; t < 4; t++) {
        int f = tid + t * 256;
        int row = f >> 4;
        int col = f & 15;
        Xs[row][col] = (rbase + row < N_NODES)
                       ? g_g3[(size_t)(rbase + row) * H2 + col] : 0.f;
    }
    __syncthreads();
#pragma unroll
    for (int t = 0; t < 10; t++) {
        int o = tid + t * 256;
        int r = o / C_OUT;
        int c = o % C_OUT;
        float acc = Bs[c];
#pragma unroll
        for (int k = 0; k < 16; k++) acc += Xs[r][k] * Ws[k * C_OUT + c];
        if (rbase + r < N_NODES)
            out[(size_t)(rbase + r) * C_OUT + c] = acc;
    }
}

// ---------------- launch: fork (fast gemm1 on side stream) ------------------
extern "C" void kernel_launch(void* const* d_in, const int* in_sizes, int n_in,
                              void* d_out, int out_size) {
    const float* x  = (const float*)d_in[0];
    const int*   ei = (const int*)d_in[1];     // int32 (JAX x64 disabled)
    const float* W1 = (const float*)d_in[2];
    const float* b1 = (const float*)d_in[3];
    const float* W2 = (const float*)d_in[4];
    const float* b2 = (const float*)d_in[5];
    const float* W3 = (const float*)d_in[6];
    const float* b3 = (const float*)d_in[7];
    float* out = (float*)d_out;

    static cudaStream_t s2 = nullptr;
    static cudaEvent_t evFork = nullptr, evJoin = nullptr;
    if (s2 == nullptr) {
        cudaStreamCreateWithFlags(&s2, cudaStreamNonBlocking);
        cudaEventCreateWithFlags(&evFork, cudaEventDisableTiming);
        cudaEventCreateWithFlags(&evJoin, cudaEventDisableTiming);
        cudaFuncSetAttribute(k_gemm1, cudaFuncAttributeMaxDynamicSharedMemorySize,
                             SMEM_G1);
    }

    const int TB = 256;
    const int gN = NBLK_N;                       // 391
    const int gE = (E_EDGES + TB - 1) / TB;      // 12500

    // fork: W1-split + GEMM1 on side stream; CSR build on main stream.
    cudaEventRecord(evFork, 0);
    cudaStreamWaitEvent(s2, evFork, 0);
    k_prepw<<<(F_IN * H1 + TB - 1) / TB, TB, 0, s2>>>(W1);   // submit 1

    k_hist<<<gE, TB>>>(ei);                                   // submit 2
    k_scan_block<<<gN, TB>>>();                               // submit 3

    k_gemm1<<<(N_NODES + 127) / 128, 256, SMEM_G1, s2>>>(x);  // submit 4 (profiled)
    cudaEventRecord(evJoin, s2);

    k_scan_sums<<<1, 512>>>(gN);                              // submit 5
    k_scan_fixup<<<gN, TB>>>();                               // submit 6
    k_fill_edge<<<gE, TB>>>(ei);                              // submit 7

    // join: aggregation needs both CSR and h1
    cudaStreamWaitEvent(0, evJoin, 0);

    k_agg1<<<(N_NODES + 63) / 64, 256>>>(b1, W2);   // fused agg1 + gemm2
    k_agg2<<<(N_NODES + 31) / 32, 256>>>(b2);
    k_agg3g<<<(N_NODES + 31) / 32, 256>>>();
    k_gemm3<<<(N_NODES + 63) / 64, 256>>>(W3, b3, out);
}